// round 1
// baseline (speedup 1.0000x reference)
#include <cuda_runtime.h>
#include <cuda_bf16.h>
#include <math.h>

// Problem constants
#define NE  160     // experts
#define CAP 120     // capacity per expert
#define NS  3200    // sequence length
#define NH  2048    // hidden dim
#define NI  192     // ffn dim per device
#define NK  6       // top-k

// Scratch (no cudaMalloc allowed): h = silu(g)*u  [E,CAP,I], o = h @ down^T [E,CAP,H]
__device__ float g_h[(size_t)NE * CAP * NI];          // 14.7 MB
__device__ float g_o[(size_t)NE * CAP * NH];          // 157  MB

// ---------------------------------------------------------------------------
// Kernel 1: gathered gate/up GEMM + SiLU
//   grid = (3 I-tiles of 64, NE experts), block = 256 (tx=32 over i, ty=8 over cap)
//   Each thread: 15 cap rows x 2 i cols x {gate,up} = 60 fp32 accumulators.
// ---------------------------------------------------------------------------
__global__ __launch_bounds__(256) void k_gateup(
    const float* __restrict__ hs,   // [S,H]
    const int*   __restrict__ tok,  // [E,CAP]
    const float* __restrict__ gw,   // [E,I,H]
    const float* __restrict__ uw)   // [E,I,H]
{
    const int e  = blockIdx.y;
    const int i0 = blockIdx.x * 64;
    const int tid = threadIdx.x;
    const int tx = tid & 31;
    const int ty = tid >> 5;

    __shared__ int   toks[CAP];
    __shared__ float xs[CAP][33];   // x tile  [cap][k], padded
    __shared__ float gs[64][33];    // gate w  [i][k],   padded
    __shared__ float us[64][33];    // up w    [i][k],   padded

    if (tid < CAP) toks[tid] = tok[e * CAP + tid];

    float accg[15][2], accu[15][2];
#pragma unroll
    for (int r = 0; r < 15; r++) {
        accg[r][0] = accg[r][1] = 0.f;
        accu[r][0] = accu[r][1] = 0.f;
    }

    const float* gwe = gw + (size_t)e * NI * NH + (size_t)i0 * NH;
    const float* uwe = uw + (size_t)e * NI * NH + (size_t)i0 * NH;

    for (int k0 = 0; k0 < NH; k0 += 32) {
        __syncthreads();
        // load gathered x tile: 120x32 = 3840 elems = 15 passes of 256
#pragma unroll
        for (int p = 0; p < 15; p++) {
            int idx = tid + p * 256;
            int c  = idx >> 5;
            int kk = idx & 31;
            xs[c][kk] = hs[(size_t)toks[c] * NH + k0 + kk];
        }
        // load weight tiles: 64x32 = 2048 elems = 8 passes of 256
#pragma unroll
        for (int p = 0; p < 8; p++) {
            int idx = tid + p * 256;
            int i  = idx >> 5;
            int kk = idx & 31;
            gs[i][kk] = gwe[(size_t)i * NH + k0 + kk];
            us[i][kk] = uwe[(size_t)i * NH + k0 + kk];
        }
        __syncthreads();

#pragma unroll
        for (int kk = 0; kk < 32; kk++) {
            // lane reads column tx and tx+32: bank = (33*i + kk) % 32 -> conflict-free
            float bg0 = gs[tx][kk],      bg1 = gs[tx + 32][kk];
            float bu0 = us[tx][kk],      bu1 = us[tx + 32][kk];
#pragma unroll
            for (int r = 0; r < 15; r++) {
                float a = xs[ty * 15 + r][kk];   // broadcast within warp
                accg[r][0] = fmaf(a, bg0, accg[r][0]);
                accg[r][1] = fmaf(a, bg1, accg[r][1]);
                accu[r][0] = fmaf(a, bu0, accu[r][0]);
                accu[r][1] = fmaf(a, bu1, accu[r][1]);
            }
        }
    }

    // SiLU(g) * u -> h scratch
#pragma unroll
    for (int r = 0; r < 15; r++) {
        int c = ty * 15 + r;
        float* dst = g_h + ((size_t)e * CAP + c) * NI + i0;
#pragma unroll
        for (int j = 0; j < 2; j++) {
            float g = accg[r][j];
            float u = accu[r][j];
            float hv = (g / (1.f + expf(-g))) * u;
            dst[tx + 32 * j] = hv;   // coalesced
        }
    }
}

// ---------------------------------------------------------------------------
// Kernel 2: down projection  o[e,c,h] = sum_i h[e,c,i] * down_w[e,h,i]
//   grid = (16 H-tiles of 128, NE), block = 256 (tx=32 over h, ty=8 over cap)
// ---------------------------------------------------------------------------
__global__ __launch_bounds__(256) void k_down(const float* __restrict__ dw /*[E,H,I]*/)
{
    const int e  = blockIdx.y;
    const int h0 = blockIdx.x * 128;
    const int tid = threadIdx.x;
    const int tx = tid & 31;
    const int ty = tid >> 5;

    __shared__ float hsm[CAP][33];
    __shared__ float dsm[128][33];

    float acc[15][4];
#pragma unroll
    for (int r = 0; r < 15; r++)
#pragma unroll
        for (int j = 0; j < 4; j++) acc[r][j] = 0.f;

    const float* hsrc = g_h + (size_t)e * CAP * NI;
    const float* dwe  = dw + (size_t)e * NH * NI + (size_t)h0 * NI;

    for (int k0 = 0; k0 < NI; k0 += 32) {
        __syncthreads();
#pragma unroll
        for (int p = 0; p < 15; p++) {           // 120*32 elems
            int idx = tid + p * 256;
            int c  = idx >> 5;
            int kk = idx & 31;
            hsm[c][kk] = hsrc[(size_t)c * NI + k0 + kk];
        }
#pragma unroll
        for (int p = 0; p < 16; p++) {           // 128*32 elems
            int idx = tid + p * 256;
            int hl = idx >> 5;
            int kk = idx & 31;
            dsm[hl][kk] = dwe[(size_t)hl * NI + k0 + kk];
        }
        __syncthreads();

#pragma unroll
        for (int kk = 0; kk < 32; kk++) {
            float b0 = dsm[tx][kk];
            float b1 = dsm[tx + 32][kk];
            float b2 = dsm[tx + 64][kk];
            float b3 = dsm[tx + 96][kk];
#pragma unroll
            for (int r = 0; r < 15; r++) {
                float a = hsm[ty * 15 + r][kk];
                acc[r][0] = fmaf(a, b0, acc[r][0]);
                acc[r][1] = fmaf(a, b1, acc[r][1]);
                acc[r][2] = fmaf(a, b2, acc[r][2]);
                acc[r][3] = fmaf(a, b3, acc[r][3]);
            }
        }
    }

#pragma unroll
    for (int r = 0; r < 15; r++) {
        int c = ty * 15 + r;
        float* dst = g_o + ((size_t)e * CAP + c) * NH + h0;
#pragma unroll
        for (int j = 0; j < 4; j++) dst[tx + 32 * j] = acc[r][j];   // coalesced
    }
}

// ---------------------------------------------------------------------------
// Kernel 3: permute-gather + top-k weighted combine + shared expert
//   out[s,h] = shared_out[s,h] + sum_k tw[k,s] * o_flat[re_index[k*S+s], h]
// ---------------------------------------------------------------------------
__global__ __launch_bounds__(256) void k_combine(
    const int*   __restrict__ rei,  // [K*S] permutation
    const float* __restrict__ tw,   // [K,S,1]
    const float* __restrict__ sh,   // [1,S,H]
    float*       __restrict__ out)  // [1,S,H]
{
    const int s = blockIdx.x;
    __shared__ int   rows[NK];
    __shared__ float wts[NK];
    if (threadIdx.x < NK) {
        rows[threadIdx.x] = rei[threadIdx.x * NS + s];
        wts[threadIdx.x]  = tw[threadIdx.x * NS + s];
    }
    __syncthreads();

    for (int h = threadIdx.x * 4; h < NH; h += 256 * 4) {
        float4 a = *(const float4*)(sh + (size_t)s * NH + h);
#pragma unroll
        for (int k = 0; k < NK; k++) {
            const float4 v = *(const float4*)(g_o + (size_t)rows[k] * NH + h);
            const float w = wts[k];
            a.x = fmaf(w, v.x, a.x);
            a.y = fmaf(w, v.y, a.y);
            a.z = fmaf(w, v.z, a.z);
            a.w = fmaf(w, v.w, a.w);
        }
        *(float4*)(out + (size_t)s * NH + h) = a;
    }
}

// ---------------------------------------------------------------------------
extern "C" void kernel_launch(void* const* d_in, const int* in_sizes, int n_in,
                              void* d_out, int out_size)
{
    const float* hs  = (const float*)d_in[0];   // hidden_states [S,H]
    const int*   tok = (const int*)  d_in[1];   // token_index   [E,CAP]
    const int*   rei = (const int*)  d_in[2];   // re_index      [E*CAP]
    const float* tw  = (const float*)d_in[3];   // topk_weight   [K,S,1]
    const float* sh  = (const float*)d_in[4];   // shared_out    [1,S,H]
    const float* gw  = (const float*)d_in[5];   // gate_w        [E,I,H]
    const float* uw  = (const float*)d_in[6];   // up_w          [E,I,H]
    const float* dw  = (const float*)d_in[7];   // down_w        [E,H,I]
    float* out = (float*)d_out;                 // [1,S,H] fp32

    dim3 g1(NI / 64, NE);     // 3 x 160
    k_gateup<<<g1, 256>>>(hs, tok, gw, uw);

    dim3 g2(NH / 128, NE);    // 16 x 160
    k_down<<<g2, 256>>>(dw);

    k_combine<<<NS, 256>>>(rei, tw, sh, out);
}

// round 2
// speedup vs baseline: 6.6915x; 6.6915x over previous
#include <cuda_runtime.h>
#include <cuda_bf16.h>
#include <math.h>
#include <stdint.h>

// Problem constants
#define NE  160     // experts
#define CAP 120     // capacity per expert
#define NS  3200    // sequence length
#define NH  2048    // hidden dim
#define NI  192     // ffn dim per device
#define NK  6       // top-k

#define P   36      // smem pitch (floats): conflict-free frag loads, 16B-aligned rows

// Scratch
__device__ float g_h[(size_t)NE * CAP * NI];          // 14.7 MB
__device__ float g_o[(size_t)NE * CAP * NH];          // 157  MB

// ---------------------------------------------------------------------------
// helpers
// ---------------------------------------------------------------------------
__device__ __forceinline__ void cp16(float* smem_dst, const float* gsrc) {
    uint32_t sa = (uint32_t)__cvta_generic_to_shared(smem_dst);
    asm volatile("cp.async.ca.shared.global [%0], [%1], 16;" :: "r"(sa), "l"(gsrc));
}
__device__ __forceinline__ void cp_commit() { asm volatile("cp.async.commit_group;"); }
template<int N> __device__ __forceinline__ void cp_wait() {
    asm volatile("cp.async.wait_group %0;" :: "n"(N));
}
__device__ __forceinline__ uint32_t f2tf(float x) {
    uint32_t r;
    asm("cvt.rna.tf32.f32 %0, %1;" : "=r"(r) : "f"(x));
    return r;
}
__device__ __forceinline__ void mma_tf32(float* c, const uint32_t* a, const uint32_t* b) {
    asm volatile(
        "mma.sync.aligned.m16n8k8.row.col.f32.tf32.tf32.f32 "
        "{%0,%1,%2,%3},{%4,%5,%6,%7},{%8,%9},{%0,%1,%2,%3};"
        : "+f"(c[0]), "+f"(c[1]), "+f"(c[2]), "+f"(c[3])
        : "r"(a[0]), "r"(a[1]), "r"(a[2]), "r"(a[3]), "r"(b[0]), "r"(b[1]));
}
__device__ __forceinline__ float silu(float g) { return g / (1.f + __expf(-g)); }

// ---------------------------------------------------------------------------
// Kernel 1: gathered gate/up GEMM (tf32 tensor core) + fused SiLU
//   grid = (2 I-halves of 96, NE).  block = 256 (8 warps: 4 along M x 2 along N)
//   Block tile: M=128 (CAP=120 padded), N=96 for BOTH gate and up.
//   Warp tile: 32 x 48 per matrix. K chunk = 32, 2-stage cp.async pipeline.
// ---------------------------------------------------------------------------
__global__ __launch_bounds__(256) void k_gateup(
    const float* __restrict__ hs,   // [S,H]
    const int*   __restrict__ tok,  // [E,CAP]
    const float* __restrict__ gw,   // [E,I,H]
    const float* __restrict__ uw)   // [E,I,H]
{
    extern __shared__ float smem[];
    float* As = smem;               // [2][128*P]
    float* Bg = As + 2 * 128 * P;   // [2][96*P]
    float* Bu = Bg + 2 * 96 * P;    // [2][96*P]

    const int e   = blockIdx.y;
    const int i0  = blockIdx.x * 96;
    const int tid = threadIdx.x;
    const int w   = tid >> 5;
    const int lane = tid & 31;
    const int wm  = w >> 1;        // 0..3 -> m offset wm*32
    const int wn  = w & 1;         // 0..1 -> n offset wn*48
    const int gr  = lane >> 2;     // group id 0..7
    const int tg  = lane & 3;      // thread in group

    __shared__ int toks[128];
    if (tid < CAP)                toks[tid] = tok[e * CAP + tid];
    else if (tid < 128)           toks[tid] = tok[e * CAP + CAP - 1];
    __syncthreads();

    const float* gwe = gw + ((size_t)e * NI + i0) * NH;
    const float* uwe = uw + ((size_t)e * NI + i0) * NH;

    float accg[2][6][4] = {};
    float accu[2][6][4] = {};

    const int NC = NH / 32;        // 64 chunks

    // chunk loader
    auto load_chunk = [&](int buf, int kc) {
        const int k0 = kc * 32;
        float* Ab = As + buf * 128 * P;
        float* Gb = Bg + buf * 96 * P;
        float* Ub = Bu + buf * 96 * P;
#pragma unroll
        for (int p = 0; p < 4; p++) {           // A: 128 rows x 8 f4
            int idx = tid + p * 256;
            int r = idx >> 3, c4 = (idx & 7) << 2;
            cp16(Ab + r * P + c4, hs + (size_t)toks[r] * NH + k0 + c4);
        }
#pragma unroll
        for (int p = 0; p < 3; p++) {           // Bg: 96 x 8 f4
            int idx = tid + p * 256;
            int r = idx >> 3, c4 = (idx & 7) << 2;
            cp16(Gb + r * P + c4, gwe + (size_t)r * NH + k0 + c4);
        }
#pragma unroll
        for (int p = 0; p < 3; p++) {           // Bu: 96 x 8 f4
            int idx = tid + p * 256;
            int r = idx >> 3, c4 = (idx & 7) << 2;
            cp16(Ub + r * P + c4, uwe + (size_t)r * NH + k0 + c4);
        }
    };

    load_chunk(0, 0);
    cp_commit();

    int buf = 0;
    for (int kc = 0; kc < NC; kc++) {
        if (kc + 1 < NC) {
            load_chunk(buf ^ 1, kc + 1);
            cp_commit();
            cp_wait<1>();
        } else {
            cp_wait<0>();
        }
        __syncthreads();

        const float* A  = As + buf * 128 * P + wm * 32 * P;
        const float* BG = Bg + buf * 96 * P + wn * 48 * P;
        const float* BU = Bu + buf * 96 * P + wn * 48 * P;

#pragma unroll
        for (int ks = 0; ks < 4; ks++) {
            const int ko = ks * 8;
            uint32_t a0[4], a1[4];
            a0[0] = f2tf(A[(gr     ) * P + ko + tg    ]);
            a0[1] = f2tf(A[(gr +  8) * P + ko + tg    ]);
            a0[2] = f2tf(A[(gr     ) * P + ko + tg + 4]);
            a0[3] = f2tf(A[(gr +  8) * P + ko + tg + 4]);
            a1[0] = f2tf(A[(gr + 16) * P + ko + tg    ]);
            a1[1] = f2tf(A[(gr + 24) * P + ko + tg    ]);
            a1[2] = f2tf(A[(gr + 16) * P + ko + tg + 4]);
            a1[3] = f2tf(A[(gr + 24) * P + ko + tg + 4]);
#pragma unroll
            for (int nt = 0; nt < 6; nt++) {
                uint32_t b[2];
                b[0] = f2tf(BG[(nt * 8 + gr) * P + ko + tg    ]);
                b[1] = f2tf(BG[(nt * 8 + gr) * P + ko + tg + 4]);
                mma_tf32(accg[0][nt], a0, b);
                mma_tf32(accg[1][nt], a1, b);
                b[0] = f2tf(BU[(nt * 8 + gr) * P + ko + tg    ]);
                b[1] = f2tf(BU[(nt * 8 + gr) * P + ko + tg + 4]);
                mma_tf32(accu[0][nt], a0, b);
                mma_tf32(accu[1][nt], a1, b);
            }
        }
        __syncthreads();
        buf ^= 1;
    }

    // Epilogue: h = silu(g)*u, write rows < CAP
#pragma unroll
    for (int mt = 0; mt < 2; mt++) {
        const int rb = wm * 32 + mt * 16 + gr;
#pragma unroll
        for (int half = 0; half < 2; half++) {
            const int r = rb + half * 8;
            if (r < CAP) {
                float* dst = g_h + ((size_t)e * CAP + r) * NI + i0 + wn * 48;
#pragma unroll
                for (int nt = 0; nt < 6; nt++) {
                    float g0 = accg[mt][nt][half * 2 + 0];
                    float g1 = accg[mt][nt][half * 2 + 1];
                    float u0 = accu[mt][nt][half * 2 + 0];
                    float u1 = accu[mt][nt][half * 2 + 1];
                    float2 hv = make_float2(silu(g0) * u0, silu(g1) * u1);
                    *(float2*)(dst + nt * 8 + 2 * tg) = hv;
                }
            }
        }
    }
}

// ---------------------------------------------------------------------------
// Kernel 2: down projection (tf32 tensor core)
//   o[e,c,h] = sum_i h[e,c,i] * down_w[e,h,i]
//   grid = (16 H-tiles of 128, NE).  block tile M=128 x N=128, K=192.
//   8 warps: 4 along M x 2 along N -> warp 32x64.
// ---------------------------------------------------------------------------
__global__ __launch_bounds__(256) void k_down(const float* __restrict__ dw /*[E,H,I]*/)
{
    extern __shared__ float smem[];
    float* As = smem;               // [2][128*P]
    float* Bs = As + 2 * 128 * P;   // [2][128*P]

    const int e   = blockIdx.y;
    const int h0  = blockIdx.x * 128;
    const int tid = threadIdx.x;
    const int w   = tid >> 5;
    const int lane = tid & 31;
    const int wm  = w >> 1;
    const int wn  = w & 1;
    const int gr  = lane >> 2;
    const int tg  = lane & 3;

    const float* hsrc = g_h + (size_t)e * CAP * NI;
    const float* dwe  = dw + ((size_t)e * NH + h0) * NI;

    float acc[2][8][4] = {};

    const int NC = NI / 32;    // 6 chunks

    auto load_chunk = [&](int buf, int kc) {
        const int k0 = kc * 32;
        float* Ab = As + buf * 128 * P;
        float* Bb = Bs + buf * 128 * P;
#pragma unroll
        for (int p = 0; p < 4; p++) {           // A: 128 x 8 f4 (rows>=CAP clamped)
            int idx = tid + p * 256;
            int r = idx >> 3, c4 = (idx & 7) << 2;
            int rr = r < CAP ? r : CAP - 1;
            cp16(Ab + r * P + c4, hsrc + (size_t)rr * NI + k0 + c4);
        }
#pragma unroll
        for (int p = 0; p < 4; p++) {           // B: 128 x 8 f4
            int idx = tid + p * 256;
            int r = idx >> 3, c4 = (idx & 7) << 2;
            cp16(Bb + r * P + c4, dwe + (size_t)r * NI + k0 + c4);
        }
    };

    load_chunk(0, 0);
    cp_commit();

    int buf = 0;
    for (int kc = 0; kc < NC; kc++) {
        if (kc + 1 < NC) {
            load_chunk(buf ^ 1, kc + 1);
            cp_commit();
            cp_wait<1>();
        } else {
            cp_wait<0>();
        }
        __syncthreads();

        const float* A = As + buf * 128 * P + wm * 32 * P;
        const float* B = Bs + buf * 128 * P + wn * 64 * P;

#pragma unroll
        for (int ks = 0; ks < 4; ks++) {
            const int ko = ks * 8;
            uint32_t a0[4], a1[4];
            a0[0] = f2tf(A[(gr     ) * P + ko + tg    ]);
            a0[1] = f2tf(A[(gr +  8) * P + ko + tg    ]);
            a0[2] = f2tf(A[(gr     ) * P + ko + tg + 4]);
            a0[3] = f2tf(A[(gr +  8) * P + ko + tg + 4]);
            a1[0] = f2tf(A[(gr + 16) * P + ko + tg    ]);
            a1[1] = f2tf(A[(gr + 24) * P + ko + tg    ]);
            a1[2] = f2tf(A[(gr + 16) * P + ko + tg + 4]);
            a1[3] = f2tf(A[(gr + 24) * P + ko + tg + 4]);
#pragma unroll
            for (int nt = 0; nt < 8; nt++) {
                uint32_t b[2];
                b[0] = f2tf(B[(nt * 8 + gr) * P + ko + tg    ]);
                b[1] = f2tf(B[(nt * 8 + gr) * P + ko + tg + 4]);
                mma_tf32(acc[0][nt], a0, b);
                mma_tf32(acc[1][nt], a1, b);
            }
        }
        __syncthreads();
        buf ^= 1;
    }

#pragma unroll
    for (int mt = 0; mt < 2; mt++) {
        const int rb = wm * 32 + mt * 16 + gr;
#pragma unroll
        for (int half = 0; half < 2; half++) {
            const int r = rb + half * 8;
            if (r < CAP) {
                float* dst = g_o + ((size_t)e * CAP + r) * NH + h0 + wn * 64;
#pragma unroll
                for (int nt = 0; nt < 8; nt++) {
                    float2 v = make_float2(acc[mt][nt][half * 2 + 0],
                                           acc[mt][nt][half * 2 + 1]);
                    *(float2*)(dst + nt * 8 + 2 * tg) = v;
                }
            }
        }
    }
}

// ---------------------------------------------------------------------------
// Kernel 3: permute-gather + top-k weighted combine + shared expert
// ---------------------------------------------------------------------------
__global__ __launch_bounds__(256) void k_combine(
    const int*   __restrict__ rei,  // [K*S]
    const float* __restrict__ tw,   // [K,S,1]
    const float* __restrict__ sh,   // [1,S,H]
    float*       __restrict__ out)  // [1,S,H]
{
    const int s = blockIdx.x;
    __shared__ int   rows[NK];
    __shared__ float wts[NK];
    if (threadIdx.x < NK) {
        rows[threadIdx.x] = rei[threadIdx.x * NS + s];
        wts[threadIdx.x]  = tw[threadIdx.x * NS + s];
    }
    __syncthreads();

    for (int h = threadIdx.x * 4; h < NH; h += 256 * 4) {
        float4 a = *(const float4*)(sh + (size_t)s * NH + h);
#pragma unroll
        for (int k = 0; k < NK; k++) {
            const float4 v = *(const float4*)(g_o + (size_t)rows[k] * NH + h);
            const float wv = wts[k];
            a.x = fmaf(wv, v.x, a.x);
            a.y = fmaf(wv, v.y, a.y);
            a.z = fmaf(wv, v.z, a.z);
            a.w = fmaf(wv, v.w, a.w);
        }
        *(float4*)(out + (size_t)s * NH + h) = a;
    }
}

// ---------------------------------------------------------------------------
extern "C" void kernel_launch(void* const* d_in, const int* in_sizes, int n_in,
                              void* d_out, int out_size)
{
    const float* hs  = (const float*)d_in[0];
    const int*   tok = (const int*)  d_in[1];
    const int*   rei = (const int*)  d_in[2];
    const float* tw  = (const float*)d_in[3];
    const float* sh  = (const float*)d_in[4];
    const float* gw  = (const float*)d_in[5];
    const float* uw  = (const float*)d_in[6];
    const float* dw  = (const float*)d_in[7];
    float* out = (float*)d_out;

    const int smem1 = 2 * (128 + 96 + 96) * P * 4;   // 92160 B
    const int smem2 = 2 * (128 + 128) * P * 4;       // 73728 B
    cudaFuncSetAttribute(k_gateup, cudaFuncAttributeMaxDynamicSharedMemorySize, smem1);
    cudaFuncSetAttribute(k_down,   cudaFuncAttributeMaxDynamicSharedMemorySize, smem2);

    dim3 g1(2, NE);      // 2 x 160
    k_gateup<<<g1, 256, smem1>>>(hs, tok, gw, uw);

    dim3 g2(NH / 128, NE);  // 16 x 160
    k_down<<<g2, 256, smem2>>>(dw);

    k_combine<<<NS, 256>>>(rei, tw, sh, out);
}

// round 5
// speedup vs baseline: 7.7952x; 1.1649x over previous
#include <cuda_runtime.h>
#include <cuda_bf16.h>
#include <math.h>
#include <stdint.h>

// Problem constants
#define NE  160     // experts
#define CAP 120     // capacity per expert
#define NS  3200    // sequence length
#define NH  2048    // hidden dim
#define NI  192     // ffn dim per device
#define NK  6       // top-k

#define P   36      // smem pitch (floats): conflict-free frag loads, 16B-aligned rows

// Scratch
__device__ float g_h[(size_t)NE * CAP * NI];          // 14.7 MB
__device__ float g_o[(size_t)NE * CAP * NH];          // 157  MB

// ---------------------------------------------------------------------------
// helpers
// ---------------------------------------------------------------------------
__device__ __forceinline__ void cp16(float* smem_dst, const float* gsrc) {
    uint32_t sa = (uint32_t)__cvta_generic_to_shared(smem_dst);
    asm volatile("cp.async.ca.shared.global [%0], [%1], 16;" :: "r"(sa), "l"(gsrc));
}
__device__ __forceinline__ void cp_commit() { asm volatile("cp.async.commit_group;"); }
template<int N> __device__ __forceinline__ void cp_wait() {
    asm volatile("cp.async.wait_group %0;" :: "n"(N));
}
// NOTE: no cvt.rna.tf32 — we feed raw fp32 bits to the tf32 MMA. The tensor
// pipe reads the top 19 bits (sign/exp/10-bit mantissa); low mantissa bits are
// truncated. Costs ~1 extra bit of rounding error, removes all CVT issue slots.
__device__ __forceinline__ void mma_tf32(float* c, const uint32_t* a, const uint32_t* b) {
    asm volatile(
        "mma.sync.aligned.m16n8k8.row.col.f32.tf32.tf32.f32 "
        "{%0,%1,%2,%3},{%4,%5,%6,%7},{%8,%9},{%0,%1,%2,%3};"
        : "+f"(c[0]), "+f"(c[1]), "+f"(c[2]), "+f"(c[3])
        : "r"(a[0]), "r"(a[1]), "r"(a[2]), "r"(a[3]), "r"(b[0]), "r"(b[1]));
}
__device__ __forceinline__ float silu(float g) { return g / (1.f + __expf(-g)); }
__device__ __forceinline__ uint32_t ldu(const float* p) {
    return __float_as_uint(*p);
}

// ---------------------------------------------------------------------------
// Kernel 1: gathered gate/up GEMM (tf32 tensor core) + fused SiLU
//   grid = (4 I-tiles of 48, NE).  block = 256 (8 warps: 4 along M x 2 along N)
//   Block tile: M=128 (CAP=120 padded), N=48 for BOTH gate and up.
//   Warp tile: 32 x 24 per matrix. K chunk = 32, 2-stage cp.async pipeline.
//   launch_bounds(256,2): 2 CTAs/SM -> 16 warps resident.
// ---------------------------------------------------------------------------
__global__ __launch_bounds__(256, 2) void k_gateup(
    const float* __restrict__ hs,   // [S,H]
    const int*   __restrict__ tok,  // [E,CAP]
    const float* __restrict__ gw,   // [E,I,H]
    const float* __restrict__ uw)   // [E,I,H]
{
    extern __shared__ float smem[];
    float* As = smem;               // [2][128*P]
    float* Bg = As + 2 * 128 * P;   // [2][48*P]
    float* Bu = Bg + 2 * 48 * P;    // [2][48*P]

    const int e   = blockIdx.y;
    const int i0  = blockIdx.x * 48;
    const int tid = threadIdx.x;
    const int w   = tid >> 5;
    const int lane = tid & 31;
    const int wm  = w >> 1;        // 0..3 -> m offset wm*32
    const int wn  = w & 1;         // 0..1 -> n offset wn*24
    const int gr  = lane >> 2;     // group id 0..7
    const int tg  = lane & 3;      // thread in group

    __shared__ int toks[128];
    if (tid < CAP)                toks[tid] = tok[e * CAP + tid];
    else if (tid < 128)           toks[tid] = tok[e * CAP + CAP - 1];
    __syncthreads();

    const float* gwe = gw + ((size_t)e * NI + i0) * NH;
    const float* uwe = uw + ((size_t)e * NI + i0) * NH;

    float accg[2][3][4] = {};
    float accu[2][3][4] = {};

    const int NC = NH / 32;        // 64 chunks

    auto load_chunk = [&](int buf, int kc) {
        const int k0 = kc * 32;
        float* Ab = As + buf * 128 * P;
        float* Gb = Bg + buf * 48 * P;
        float* Ub = Bu + buf * 48 * P;
#pragma unroll
        for (int p = 0; p < 4; p++) {           // A: 128 rows x 8 f4
            int idx = tid + p * 256;
            int r = idx >> 3, c4 = (idx & 7) << 2;
            cp16(Ab + r * P + c4, hs + (size_t)toks[r] * NH + k0 + c4);
        }
#pragma unroll
        for (int p = 0; p < 3; p++) {           // Bg+Bu: 2 x 48 x 8 f4 = 768
            int idx = tid + p * 256;
            if (idx < 384) {
                int r = idx >> 3, c4 = (idx & 7) << 2;
                cp16(Gb + r * P + c4, gwe + (size_t)r * NH + k0 + c4);
            } else {
                int j = idx - 384;
                int r = j >> 3, c4 = (j & 7) << 2;
                cp16(Ub + r * P + c4, uwe + (size_t)r * NH + k0 + c4);
            }
        }
    };

    load_chunk(0, 0);
    cp_commit();

    int buf = 0;
    for (int kc = 0; kc < NC; kc++) {
        if (kc + 1 < NC) {
            load_chunk(buf ^ 1, kc + 1);
            cp_commit();
            cp_wait<1>();
        } else {
            cp_wait<0>();
        }
        __syncthreads();

        const float* A  = As + buf * 128 * P + wm * 32 * P;
        const float* BG = Bg + buf * 48 * P + wn * 24 * P;
        const float* BU = Bu + buf * 48 * P + wn * 24 * P;

#pragma unroll
        for (int ks = 0; ks < 4; ks++) {
            const int ko = ks * 8;
            uint32_t a0[4], a1[4];
            a0[0] = ldu(&A[(gr     ) * P + ko + tg    ]);
            a0[1] = ldu(&A[(gr +  8) * P + ko + tg    ]);
            a0[2] = ldu(&A[(gr     ) * P + ko + tg + 4]);
            a0[3] = ldu(&A[(gr +  8) * P + ko + tg + 4]);
            a1[0] = ldu(&A[(gr + 16) * P + ko + tg    ]);
            a1[1] = ldu(&A[(gr + 24) * P + ko + tg    ]);
            a1[2] = ldu(&A[(gr + 16) * P + ko + tg + 4]);
            a1[3] = ldu(&A[(gr + 24) * P + ko + tg + 4]);
#pragma unroll
            for (int nt = 0; nt < 3; nt++) {
                uint32_t b[2];
                b[0] = ldu(&BG[(nt * 8 + gr) * P + ko + tg    ]);
                b[1] = ldu(&BG[(nt * 8 + gr) * P + ko + tg + 4]);
                mma_tf32(accg[0][nt], a0, b);
                mma_tf32(accg[1][nt], a1, b);
                b[0] = ldu(&BU[(nt * 8 + gr) * P + ko + tg    ]);
                b[1] = ldu(&BU[(nt * 8 + gr) * P + ko + tg + 4]);
                mma_tf32(accu[0][nt], a0, b);
                mma_tf32(accu[1][nt], a1, b);
            }
        }
        __syncthreads();
        buf ^= 1;
    }

    // Epilogue: h = silu(g)*u, write rows < CAP
#pragma unroll
    for (int mt = 0; mt < 2; mt++) {
#pragma unroll
        for (int half = 0; half < 2; half++) {
            const int r = wm * 32 + mt * 16 + gr + half * 8;
            if (r < CAP) {
                float* dst = g_h + ((size_t)e * CAP + r) * NI + i0 + wn * 24;
#pragma unroll
                for (int nt = 0; nt < 3; nt++) {
                    float g0 = accg[mt][nt][half * 2 + 0];
                    float g1 = accg[mt][nt][half * 2 + 1];
                    float u0 = accu[mt][nt][half * 2 + 0];
                    float u1 = accu[mt][nt][half * 2 + 1];
                    float2 hv = make_float2(silu(g0) * u0, silu(g1) * u1);
                    *(float2*)(dst + nt * 8 + 2 * tg) = hv;
                }
            }
        }
    }
}

// ---------------------------------------------------------------------------
// Kernel 2: down projection (tf32 tensor core)
//   o[e,c,h] = sum_i h[e,c,i] * down_w[e,h,i]
//   grid = (16 H-tiles of 128, NE).  block tile M=128 x N=128, K=192.
//   8 warps: 4 along M x 2 along N -> warp 32x64.
// ---------------------------------------------------------------------------
__global__ __launch_bounds__(256, 2) void k_down(const float* __restrict__ dw /*[E,H,I]*/)
{
    extern __shared__ float smem[];
    float* As = smem;               // [2][128*P]
    float* Bs = As + 2 * 128 * P;   // [2][128*P]

    const int e   = blockIdx.y;
    const int h0  = blockIdx.x * 128;
    const int tid = threadIdx.x;
    const int w   = tid >> 5;
    const int lane = tid & 31;
    const int wm  = w >> 1;
    const int wn  = w & 1;
    const int gr  = lane >> 2;
    const int tg  = lane & 3;

    const float* hsrc = g_h + (size_t)e * CAP * NI;
    const float* dwe  = dw + ((size_t)e * NH + h0) * NI;

    float acc[2][8][4] = {};

    const int NC = NI / 32;    // 6 chunks

    auto load_chunk = [&](int buf, int kc) {
        const int k0 = kc * 32;
        float* Ab = As + buf * 128 * P;
        float* Bb = Bs + buf * 128 * P;
#pragma unroll
        for (int p = 0; p < 4; p++) {           // A: 128 x 8 f4 (rows>=CAP clamped)
            int idx = tid + p * 256;
            int r = idx >> 3, c4 = (idx & 7) << 2;
            int rr = r < CAP ? r : CAP - 1;
            cp16(Ab + r * P + c4, hsrc + (size_t)rr * NI + k0 + c4);
        }
#pragma unroll
        for (int p = 0; p < 4; p++) {           // B: 128 x 8 f4
            int idx = tid + p * 256;
            int r = idx >> 3, c4 = (idx & 7) << 2;
            cp16(Bb + r * P + c4, dwe + (size_t)r * NI + k0 + c4);
        }
    };

    load_chunk(0, 0);
    cp_commit();

    int buf = 0;
    for (int kc = 0; kc < NC; kc++) {
        if (kc + 1 < NC) {
            load_chunk(buf ^ 1, kc + 1);
            cp_commit();
            cp_wait<1>();
        } else {
            cp_wait<0>();
        }
        __syncthreads();

        const float* A = As + buf * 128 * P + wm * 32 * P;
        const float* B = Bs + buf * 128 * P + wn * 64 * P;

#pragma unroll
        for (int ks = 0; ks < 4; ks++) {
            const int ko = ks * 8;
            uint32_t a0[4], a1[4];
            a0[0] = ldu(&A[(gr     ) * P + ko + tg    ]);
            a0[1] = ldu(&A[(gr +  8) * P + ko + tg    ]);
            a0[2] = ldu(&A[(gr     ) * P + ko + tg + 4]);
            a0[3] = ldu(&A[(gr +  8) * P + ko + tg + 4]);
            a1[0] = ldu(&A[(gr + 16) * P + ko + tg    ]);
            a1[1] = ldu(&A[(gr + 24) * P + ko + tg    ]);
            a1[2] = ldu(&A[(gr + 16) * P + ko + tg + 4]);
            a1[3] = ldu(&A[(gr + 24) * P + ko + tg + 4]);
#pragma unroll
            for (int nt = 0; nt < 8; nt++) {
                uint32_t b[2];
                b[0] = ldu(&B[(nt * 8 + gr) * P + ko + tg    ]);
                b[1] = ldu(&B[(nt * 8 + gr) * P + ko + tg + 4]);
                mma_tf32(acc[0][nt], a0, b);
                mma_tf32(acc[1][nt], a1, b);
            }
        }
        __syncthreads();
        buf ^= 1;
    }

#pragma unroll
    for (int mt = 0; mt < 2; mt++) {
#pragma unroll
        for (int half = 0; half < 2; half++) {
            const int r = wm * 32 + mt * 16 + gr + half * 8;
            if (r < CAP) {
                float* dst = g_o + ((size_t)e * CAP + r) * NH + h0 + wn * 64;
#pragma unroll
                for (int nt = 0; nt < 8; nt++) {
                    float2 v = make_float2(acc[mt][nt][half * 2 + 0],
                                           acc[mt][nt][half * 2 + 1]);
                    *(float2*)(dst + nt * 8 + 2 * tg) = v;
                }
            }
        }
    }
}

// ---------------------------------------------------------------------------
// Kernel 3: permute-gather + top-k weighted combine + shared expert
// ---------------------------------------------------------------------------
__global__ __launch_bounds__(256) void k_combine(
    const int*   __restrict__ rei,  // [K*S]
    const float* __restrict__ tw,   // [K,S,1]
    const float* __restrict__ sh,   // [1,S,H]
    float*       __restrict__ out)  // [1,S,H]
{
    const int s = blockIdx.x;
    __shared__ int   rows[NK];
    __shared__ float wts[NK];
    if (threadIdx.x < NK) {
        rows[threadIdx.x] = rei[threadIdx.x * NS + s];
        wts[threadIdx.x]  = tw[threadIdx.x * NS + s];
    }
    __syncthreads();

    for (int h = threadIdx.x * 4; h < NH; h += 256 * 4) {
        float4 a = *(const float4*)(sh + (size_t)s * NH + h);
#pragma unroll
        for (int k = 0; k < NK; k++) {
            const float4 v = *(const float4*)(g_o + (size_t)rows[k] * NH + h);
            const float wv = wts[k];
            a.x = fmaf(wv, v.x, a.x);
            a.y = fmaf(wv, v.y, a.y);
            a.z = fmaf(wv, v.z, a.z);
            a.w = fmaf(wv, v.w, a.w);
        }
        *(float4*)(out + (size_t)s * NH + h) = a;
    }
}

// ---------------------------------------------------------------------------
extern "C" void kernel_launch(void* const* d_in, const int* in_sizes, int n_in,
                              void* d_out, int out_size)
{
    const float* hs  = (const float*)d_in[0];
    const int*   tok = (const int*)  d_in[1];
    const int*   rei = (const int*)  d_in[2];
    const float* tw  = (const float*)d_in[3];
    const float* sh  = (const float*)d_in[4];
    const float* gw  = (const float*)d_in[5];
    const float* uw  = (const float*)d_in[6];
    const float* dw  = (const float*)d_in[7];
    float* out = (float*)d_out;

    const int smem1 = 2 * (128 + 48 + 48) * P * 4;   // 64512 B
    const int smem2 = 2 * (128 + 128) * P * 4;       // 73728 B
    cudaFuncSetAttribute(k_gateup, cudaFuncAttributeMaxDynamicSharedMemorySize, smem1);
    cudaFuncSetAttribute(k_down,   cudaFuncAttributeMaxDynamicSharedMemorySize, smem2);

    dim3 g1(4, NE);      // 4 x 160 = 640 blocks
    k_gateup<<<g1, 256, smem1>>>(hs, tok, gw, uw);

    dim3 g2(NH / 128, NE);  // 16 x 160 = 2560 blocks
    k_down<<<g2, 256, smem2>>>(dw);

    k_combine<<<NS, 256>>>(rei, tw, sh, out);
}

// round 7
// speedup vs baseline: 8.4686x; 1.0864x over previous
#include <cuda_runtime.h>
#include <cuda_bf16.h>
#include <math.h>
#include <stdint.h>

// Problem constants
#define NE  160     // experts
#define CAP 120     // capacity per expert
#define NS  3200    // sequence length
#define NH  2048    // hidden dim
#define NI  192     // ffn dim per device
#define NK  6       // top-k

#define P   40      // smem pitch (floats): 40*gr mod 32 cycles {0,8,16,24} ->
                    // float2 (LDS.64) fragment loads are bank-conflict-free

// Scratch
__device__ float g_h[(size_t)NE * CAP * NI];          // 14.7 MB
__device__ float g_o[(size_t)NE * CAP * NH];          // 157  MB

// ---------------------------------------------------------------------------
// helpers
// ---------------------------------------------------------------------------
__device__ __forceinline__ void cp16(float* smem_dst, const float* gsrc) {
    uint32_t sa = (uint32_t)__cvta_generic_to_shared(smem_dst);
    asm volatile("cp.async.ca.shared.global [%0], [%1], 16;" :: "r"(sa), "l"(gsrc));
}
__device__ __forceinline__ void cp_commit() { asm volatile("cp.async.commit_group;"); }
template<int N> __device__ __forceinline__ void cp_wait() {
    asm volatile("cp.async.wait_group %0;" :: "n"(N));
}
// pack float2 {lo,hi} -> f16x2 register (lo in bits [0:16))
__device__ __forceinline__ uint32_t pk(float2 v) {
    uint32_t r;
    asm("cvt.rn.f16x2.f32 %0, %1, %2;" : "=r"(r) : "f"(v.y), "f"(v.x));
    return r;
}
// m16n8k16 fp16 MMA, fp32 accumulate: 2048 MACs/instr (2x tf32 m16n8k8 rate)
__device__ __forceinline__ void mma_f16(float* c, const uint32_t* a, const uint32_t* b) {
    asm volatile(
        "mma.sync.aligned.m16n8k16.row.col.f32.f16.f16.f32 "
        "{%0,%1,%2,%3},{%4,%5,%6,%7},{%8,%9},{%0,%1,%2,%3};"
        : "+f"(c[0]), "+f"(c[1]), "+f"(c[2]), "+f"(c[3])
        : "r"(a[0]), "r"(a[1]), "r"(a[2]), "r"(a[3]), "r"(b[0]), "r"(b[1]));
}
__device__ __forceinline__ float silu(float g) { return g / (1.f + __expf(-g)); }
__device__ __forceinline__ float2 ld2(const float* p) { return *(const float2*)p; }

// ---------------------------------------------------------------------------
// Kernel 1: gathered gate/up GEMM (fp16 tensor core, fp32 accum) + fused SiLU
//   grid = (4 I-tiles of 48, NE).  block = 256 (8 warps: 4 along M x 2 along N)
//   Block tile: M=128 (CAP=120 padded), N=48 for BOTH gate and up.
//   Warp tile: 32 x 24 per matrix. K chunk = 32 (2 k16 steps), 2-stage cp.async.
//   launch_bounds(256,2): 2 CTAs/SM.
// ---------------------------------------------------------------------------
__global__ __launch_bounds__(256, 2) void k_gateup(
    const float* __restrict__ hs,   // [S,H]
    const int*   __restrict__ tok,  // [E,CAP]
    const float* __restrict__ gw,   // [E,I,H]
    const float* __restrict__ uw)   // [E,I,H]
{
    extern __shared__ float smem[];
    float* As = smem;               // [2][128*P]
    float* Bg = As + 2 * 128 * P;   // [2][48*P]
    float* Bu = Bg + 2 * 48 * P;    // [2][48*P]

    const int e   = blockIdx.y;
    const int i0  = blockIdx.x * 48;
    const int tid = threadIdx.x;
    const int w   = tid >> 5;
    const int lane = tid & 31;
    const int wm  = w >> 1;        // 0..3 -> m offset wm*32
    const int wn  = w & 1;         // 0..1 -> n offset wn*24
    const int gr  = lane >> 2;     // group id 0..7
    const int tg  = lane & 3;      // thread in group

    __shared__ int toks[128];
    if (tid < CAP)                toks[tid] = tok[e * CAP + tid];
    else if (tid < 128)           toks[tid] = tok[e * CAP + CAP - 1];
    __syncthreads();

    const float* gwe = gw + ((size_t)e * NI + i0) * NH;
    const float* uwe = uw + ((size_t)e * NI + i0) * NH;

    float accg[2][3][4] = {};
    float accu[2][3][4] = {};

    const int NC = NH / 32;        // 64 chunks

    auto load_chunk = [&](int buf, int kc) {
        const int k0 = kc * 32;
        float* Ab = As + buf * 128 * P;
        float* Gb = Bg + buf * 48 * P;
        float* Ub = Bu + buf * 48 * P;
#pragma unroll
        for (int p = 0; p < 4; p++) {           // A: 128 rows x 8 f4
            int idx = tid + p * 256;
            int r = idx >> 3, c4 = (idx & 7) << 2;
            cp16(Ab + r * P + c4, hs + (size_t)toks[r] * NH + k0 + c4);
        }
#pragma unroll
        for (int p = 0; p < 3; p++) {           // Bg+Bu: 2 x 48 x 8 f4 = 768
            int idx = tid + p * 256;
            if (idx < 384) {
                int r = idx >> 3, c4 = (idx & 7) << 2;
                cp16(Gb + r * P + c4, gwe + (size_t)r * NH + k0 + c4);
            } else {
                int j = idx - 384;
                int r = j >> 3, c4 = (j & 7) << 2;
                cp16(Ub + r * P + c4, uwe + (size_t)r * NH + k0 + c4);
            }
        }
    };

    load_chunk(0, 0);
    cp_commit();

    int buf = 0;
    for (int kc = 0; kc < NC; kc++) {
        if (kc + 1 < NC) {
            load_chunk(buf ^ 1, kc + 1);
            cp_commit();
            cp_wait<1>();
        } else {
            cp_wait<0>();
        }
        __syncthreads();

        const float* A  = As + buf * 128 * P + wm * 32 * P;
        const float* BG = Bg + buf * 48 * P + wn * 24 * P;
        const float* BU = Bu + buf * 48 * P + wn * 24 * P;

#pragma unroll
        for (int ks = 0; ks < 2; ks++) {        // 2 k16 steps per 32-chunk
            const int ko = ks * 16;
            const int c0 = ko + 2 * tg;
            uint32_t a0[4], a1[4];
            a0[0] = pk(ld2(&A[(gr     ) * P + c0    ]));
            a0[1] = pk(ld2(&A[(gr +  8) * P + c0    ]));
            a0[2] = pk(ld2(&A[(gr     ) * P + c0 + 8]));
            a0[3] = pk(ld2(&A[(gr +  8) * P + c0 + 8]));
            a1[0] = pk(ld2(&A[(gr + 16) * P + c0    ]));
            a1[1] = pk(ld2(&A[(gr + 24) * P + c0    ]));
            a1[2] = pk(ld2(&A[(gr + 16) * P + c0 + 8]));
            a1[3] = pk(ld2(&A[(gr + 24) * P + c0 + 8]));
#pragma unroll
            for (int nt = 0; nt < 3; nt++) {
                uint32_t b[2];
                b[0] = pk(ld2(&BG[(nt * 8 + gr) * P + c0    ]));
                b[1] = pk(ld2(&BG[(nt * 8 + gr) * P + c0 + 8]));
                mma_f16(accg[0][nt], a0, b);
                mma_f16(accg[1][nt], a1, b);
                b[0] = pk(ld2(&BU[(nt * 8 + gr) * P + c0    ]));
                b[1] = pk(ld2(&BU[(nt * 8 + gr) * P + c0 + 8]));
                mma_f16(accu[0][nt], a0, b);
                mma_f16(accu[1][nt], a1, b);
            }
        }
        __syncthreads();
        buf ^= 1;
    }

    // Epilogue: h = silu(g)*u, write rows < CAP
#pragma unroll
    for (int mt = 0; mt < 2; mt++) {
#pragma unroll
        for (int half = 0; half < 2; half++) {
            const int r = wm * 32 + mt * 16 + gr + half * 8;
            if (r < CAP) {
                float* dst = g_h + ((size_t)e * CAP + r) * NI + i0 + wn * 24;
#pragma unroll
                for (int nt = 0; nt < 3; nt++) {
                    float g0 = accg[mt][nt][half * 2 + 0];
                    float g1 = accg[mt][nt][half * 2 + 1];
                    float u0 = accu[mt][nt][half * 2 + 0];
                    float u1 = accu[mt][nt][half * 2 + 1];
                    float2 hv = make_float2(silu(g0) * u0, silu(g1) * u1);
                    *(float2*)(dst + nt * 8 + 2 * tg) = hv;
                }
            }
        }
    }
}

// ---------------------------------------------------------------------------
// Kernel 2: down projection (fp16 tensor core, fp32 accum)
//   o[e,c,h] = sum_i h[e,c,i] * down_w[e,h,i]
//   grid = (16 H-tiles of 128, NE).  block tile M=128 x N=128, K=192.
//   8 warps: 4 along M x 2 along N -> warp 32x64.
// ---------------------------------------------------------------------------
__global__ __launch_bounds__(256, 2) void k_down(const float* __restrict__ dw /*[E,H,I]*/)
{
    extern __shared__ float smem[];
    float* As = smem;               // [2][128*P]
    float* Bs = As + 2 * 128 * P;   // [2][128*P]

    const int e   = blockIdx.y;
    const int h0  = blockIdx.x * 128;
    const int tid = threadIdx.x;
    const int w   = tid >> 5;
    const int lane = tid & 31;
    const int wm  = w >> 1;
    const int wn  = w & 1;
    const int gr  = lane >> 2;
    const int tg  = lane & 3;

    const float* hsrc = g_h + (size_t)e * CAP * NI;
    const float* dwe  = dw + ((size_t)e * NH + h0) * NI;

    float acc[2][8][4] = {};

    const int NC = NI / 32;    // 6 chunks

    auto load_chunk = [&](int buf, int kc) {
        const int k0 = kc * 32;
        float* Ab = As + buf * 128 * P;
        float* Bb = Bs + buf * 128 * P;
#pragma unroll
        for (int p = 0; p < 4; p++) {           // A: 128 x 8 f4 (rows>=CAP clamped)
            int idx = tid + p * 256;
            int r = idx >> 3, c4 = (idx & 7) << 2;
            int rr = r < CAP ? r : CAP - 1;
            cp16(Ab + r * P + c4, hsrc + (size_t)rr * NI + k0 + c4);
        }
#pragma unroll
        for (int p = 0; p < 4; p++) {           // B: 128 x 8 f4
            int idx = tid + p * 256;
            int r = idx >> 3, c4 = (idx & 7) << 2;
            cp16(Bb + r * P + c4, dwe + (size_t)r * NI + k0 + c4);
        }
    };

    load_chunk(0, 0);
    cp_commit();

    int buf = 0;
    for (int kc = 0; kc < NC; kc++) {
        if (kc + 1 < NC) {
            load_chunk(buf ^ 1, kc + 1);
            cp_commit();
            cp_wait<1>();
        } else {
            cp_wait<0>();
        }
        __syncthreads();

        const float* A = As + buf * 128 * P + wm * 32 * P;
        const float* B = Bs + buf * 128 * P + wn * 64 * P;

#pragma unroll
        for (int ks = 0; ks < 2; ks++) {        // 2 k16 steps per 32-chunk
            const int ko = ks * 16;
            const int c0 = ko + 2 * tg;
            uint32_t a0[4], a1[4];
            a0[0] = pk(ld2(&A[(gr     ) * P + c0    ]));
            a0[1] = pk(ld2(&A[(gr +  8) * P + c0    ]));
            a0[2] = pk(ld2(&A[(gr     ) * P + c0 + 8]));
            a0[3] = pk(ld2(&A[(gr +  8) * P + c0 + 8]));
            a1[0] = pk(ld2(&A[(gr + 16) * P + c0    ]));
            a1[1] = pk(ld2(&A[(gr + 24) * P + c0    ]));
            a1[2] = pk(ld2(&A[(gr + 16) * P + c0 + 8]));
            a1[3] = pk(ld2(&A[(gr + 24) * P + c0 + 8]));
#pragma unroll
            for (int nt = 0; nt < 8; nt++) {
                uint32_t b[2];
                b[0] = pk(ld2(&B[(nt * 8 + gr) * P + c0    ]));
                b[1] = pk(ld2(&B[(nt * 8 + gr) * P + c0 + 8]));
                mma_f16(acc[0][nt], a0, b);
                mma_f16(acc[1][nt], a1, b);
            }
        }
        __syncthreads();
        buf ^= 1;
    }

#pragma unroll
    for (int mt = 0; mt < 2; mt++) {
#pragma unroll
        for (int half = 0; half < 2; half++) {
            const int r = wm * 32 + mt * 16 + gr + half * 8;
            if (r < CAP) {
                float* dst = g_o + ((size_t)e * CAP + r) * NH + h0 + wn * 64;
#pragma unroll
                for (int nt = 0; nt < 8; nt++) {
                    float2 v = make_float2(acc[mt][nt][half * 2 + 0],
                                           acc[mt][nt][half * 2 + 1]);
                    *(float2*)(dst + nt * 8 + 2 * tg) = v;
                }
            }
        }
    }
}

// ---------------------------------------------------------------------------
// Kernel 3: permute-gather + top-k weighted combine + shared expert
// ---------------------------------------------------------------------------
__global__ __launch_bounds__(256) void k_combine(
    const int*   __restrict__ rei,  // [K*S]
    const float* __restrict__ tw,   // [K,S,1]
    const float* __restrict__ sh,   // [1,S,H]
    float*       __restrict__ out)  // [1,S,H]
{
    const int s = blockIdx.x;
    __shared__ int   rows[NK];
    __shared__ float wts[NK];
    if (threadIdx.x < NK) {
        rows[threadIdx.x] = rei[threadIdx.x * NS + s];
        wts[threadIdx.x]  = tw[threadIdx.x * NS + s];
    }
    __syncthreads();

    for (int h = threadIdx.x * 4; h < NH; h += 256 * 4) {
        float4 a = *(const float4*)(sh + (size_t)s * NH + h);
#pragma unroll
        for (int k = 0; k < NK; k++) {
            const float4 v = *(const float4*)(g_o + (size_t)rows[k] * NH + h);
            const float wv = wts[k];
            a.x = fmaf(wv, v.x, a.x);
            a.y = fmaf(wv, v.y, a.y);
            a.z = fmaf(wv, v.z, a.z);
            a.w = fmaf(wv, v.w, a.w);
        }
        *(float4*)(out + (size_t)s * NH + h) = a;
    }
}

// ---------------------------------------------------------------------------
extern "C" void kernel_launch(void* const* d_in, const int* in_sizes, int n_in,
                              void* d_out, int out_size)
{
    const float* hs  = (const float*)d_in[0];
    const int*   tok = (const int*)  d_in[1];
    const int*   rei = (const int*)  d_in[2];
    const float* tw  = (const float*)d_in[3];
    const float* sh  = (const float*)d_in[4];
    const float* gw  = (const float*)d_in[5];
    const float* uw  = (const float*)d_in[6];
    const float* dw  = (const float*)d_in[7];
    float* out = (float*)d_out;

    const int smem1 = 2 * (128 + 48 + 48) * P * 4;   // 71680 B
    const int smem2 = 2 * (128 + 128) * P * 4;       // 81920 B
    cudaFuncSetAttribute(k_gateup, cudaFuncAttributeMaxDynamicSharedMemorySize, smem1);
    cudaFuncSetAttribute(k_down,   cudaFuncAttributeMaxDynamicSharedMemorySize, smem2);

    dim3 g1(4, NE);      // 640 blocks
    k_gateup<<<g1, 256, smem1>>>(hs, tok, gw, uw);

    dim3 g2(NH / 128, NE);  // 2560 blocks
    k_down<<<g2, 256, smem2>>>(dw);

    k_combine<<<NS, 256>>>(rei, tw, sh, out);
}